// round 9
// baseline (speedup 1.0000x reference)
#include <cuda_runtime.h>
#include <cuda_bf16.h>
#include <cstdint>

#define SS 4
#define NN 4096
#define DD 64
#define TM 64     // i rows per CTA
#define TN 64     // j rows per CTA

// Pre-split bf16 hi/lo operand arrays (2 MB each, static — no allocs allowed)
__device__ __nv_bfloat16 g_Ah[(size_t)SS * NN * DD];
__device__ __nv_bfloat16 g_Al[(size_t)SS * NN * DD];
__device__ __nv_bfloat16 g_Bh[(size_t)SS * NN * DD];
__device__ __nv_bfloat16 g_Bl[(size_t)SS * NN * DD];

__device__ __forceinline__ uint32_t pkbf2(float a, float b) {
    __nv_bfloat162 t = __floats2bfloat162_rn(a, b);
    return *(uint32_t*)&t;
}

// ---------------------------------------------------------------------------
// Stage 1 (fused): blocks [0,128):  Q = x0 @ W^T, split -> g_Bh/g_Bl
//                  blocks [128,384): split x1 -> g_Ah/g_Al
// ---------------------------------------------------------------------------
__global__ __launch_bounds__(256) void prep_kernel(const float* __restrict__ x0,
                                                   const float* __restrict__ x1,
                                                   const float* __restrict__ W) {
    const int tid = threadIdx.x;
    if (blockIdx.x < 128) {
        __shared__ float Ws[DD * DD];
        #pragma unroll
        for (int i = tid; i < DD * DD / 4; i += 256)
            ((float4*)Ws)[i] = ((const float4*)W)[i];
        __syncthreads();

        int gid = blockIdx.x * 256 + tid;      // 0 .. 2*S*N-1
        int row = gid >> 1;
        int half = gid & 1;                    // 32 d-outputs

        const float4* xr = (const float4*)(x0 + (size_t)row * DD);
        float4 x[16];
        #pragma unroll
        for (int e = 0; e < 16; ++e) x[e] = xr[e];

        uint2* qh = (uint2*)(g_Bh + (size_t)row * DD + half * 32);
        uint2* ql = (uint2*)(g_Bl + (size_t)row * DD + half * 32);
        #pragma unroll
        for (int d4 = 0; d4 < 8; ++d4) {
            float r[4];
            #pragma unroll
            for (int dd = 0; dd < 4; ++dd) {
                int d = half * 32 + d4 * 4 + dd;
                const float4* wr = (const float4*)(Ws + d * DD);
                float a0 = 0.f, a1 = 0.f, a2 = 0.f, a3 = 0.f;
                #pragma unroll
                for (int e4 = 0; e4 < 16; e4 += 4) {
                    float4 w0 = wr[e4 + 0], w1 = wr[e4 + 1], w2 = wr[e4 + 2], w3 = wr[e4 + 3];
                    a0 += x[e4 + 0].x * w0.x + x[e4 + 0].y * w0.y + x[e4 + 0].z * w0.z + x[e4 + 0].w * w0.w;
                    a1 += x[e4 + 1].x * w1.x + x[e4 + 1].y * w1.y + x[e4 + 1].z * w1.z + x[e4 + 1].w * w1.w;
                    a2 += x[e4 + 2].x * w2.x + x[e4 + 2].y * w2.y + x[e4 + 2].z * w2.z + x[e4 + 2].w * w2.w;
                    a3 += x[e4 + 3].x * w3.x + x[e4 + 3].y * w3.y + x[e4 + 3].z * w3.z + x[e4 + 3].w * w3.w;
                }
                r[dd] = (a0 + a1) + (a2 + a3);
            }
            float h0 = __bfloat162float(__float2bfloat16(r[0]));
            float h1 = __bfloat162float(__float2bfloat16(r[1]));
            float h2 = __bfloat162float(__float2bfloat16(r[2]));
            float h3 = __bfloat162float(__float2bfloat16(r[3]));
            qh[d4] = make_uint2(pkbf2(h0, h1), pkbf2(h2, h3));
            ql[d4] = make_uint2(pkbf2(r[0] - h0, r[1] - h1), pkbf2(r[2] - h2, r[3] - h3));
        }
    } else {
        // x1 split: 256 blocks over 262144 float4 (4 grid-strided iters)
        int idx = (blockIdx.x - 128) * 256 + tid;
        const float4* src = (const float4*)x1;
        uint2* ah = (uint2*)g_Ah;
        uint2* al = (uint2*)g_Al;
        #pragma unroll
        for (int it = 0; it < 4; ++it) {
            int i = it * 65536 + idx;
            float4 v = src[i];
            float hx = __bfloat162float(__float2bfloat16(v.x));
            float hy = __bfloat162float(__float2bfloat16(v.y));
            float hz = __bfloat162float(__float2bfloat16(v.z));
            float hw = __bfloat162float(__float2bfloat16(v.w));
            ah[i] = make_uint2(pkbf2(hx, hy), pkbf2(hz, hw));
            al[i] = make_uint2(pkbf2(v.x - hx, v.y - hy), pkbf2(v.z - hz, v.w - hw));
        }
    }
}

// ---------------------------------------------------------------------------
// Baseline-PTX tensor core helpers
// ---------------------------------------------------------------------------
__device__ __forceinline__ uint32_t smem_u32(const void* p) {
    uint32_t a;
    asm("{ .reg .u64 t; cvta.to.shared.u64 t, %1; cvt.u32.u64 %0, t; }" : "=r"(a) : "l"(p));
    return a;
}

__device__ __forceinline__ void ldsm4(uint32_t* r, uint32_t addr) {
    asm volatile("ldmatrix.sync.aligned.m8n8.x4.shared.b16 {%0,%1,%2,%3}, [%4];"
                 : "=r"(r[0]), "=r"(r[1]), "=r"(r[2]), "=r"(r[3]) : "r"(addr));
}

__device__ __forceinline__ void mma16816(float* c, const uint32_t* a,
                                         const uint32_t* b) {
    asm volatile(
        "mma.sync.aligned.m16n8k16.row.col.f32.bf16.bf16.f32 "
        "{%0,%1,%2,%3}, {%4,%5,%6,%7}, {%8,%9}, {%0,%1,%2,%3};"
        : "+f"(c[0]), "+f"(c[1]), "+f"(c[2]), "+f"(c[3])
        : "r"(a[0]), "r"(a[1]), "r"(a[2]), "r"(a[3]), "r"(b[0]), "r"(b[1]));
}

__device__ __forceinline__ void stcs2(float* p, float2 v) {
    asm volatile("st.global.cs.v2.f32 [%0], {%1,%2};" :: "l"(p), "f"(v.x), "f"(v.y)
                 : "memory");
}

__device__ __forceinline__ void cpasync16(uint32_t dst, const void* src) {
    asm volatile("cp.async.cg.shared.global [%0], [%1], 16;" :: "r"(dst), "l"(src)
                 : "memory");
}

// SMEM: pitch-144 rows (conflict-free ldmatrix). A: 64 rows, B: 64 rows.
#define PITCHB 144
#define SM_AH  0
#define SM_AL  (TM * PITCHB)                        // 9216
#define SM_BH  (2 * TM * PITCHB)                    // 18432
#define SM_BL  (2 * TM * PITCHB + TN * PITCHB)      // 27648
#define SM_TOTAL (2 * TM * PITCHB + 2 * TN * PITCHB)  // 36864

// ---------------------------------------------------------------------------
// Stage 2: out[s,i,j] = sum_d x1[s,i,d] * Q[s,j,d] via bf16x3 mma.sync.
// 64x64 tile/CTA, 128 threads (4 warps, 2x2), warp tile 32x32, K=64 resident.
// Tiny CTA -> 6 CTAs/SM (24 warps) for deep cross-CTA phase overlap.
// ---------------------------------------------------------------------------
__global__ __launch_bounds__(128, 6) void gemm_mma(const float* __restrict__ bias,
                                                   float* __restrict__ out) {
    extern __shared__ char smem[];
    const uint32_t sb = smem_u32(smem);
    const int tid = threadIdx.x, wid = tid >> 5, lid = tid & 31;
    const int s = blockIdx.z, bj = blockIdx.x, bi = blockIdx.y;
    const int warp_m = wid >> 1;   // 0..1, 32 rows
    const int warp_n = wid & 1;    // 0..1, 32 cols

    // ---- Prologue: cp.async the 4 pre-split tiles (16 per thread) ----
    const size_t Abase = ((size_t)s * NN + (size_t)bi * TM) * DD;
    const size_t Bbase = ((size_t)s * NN + (size_t)bj * TN) * DD;

    #pragma unroll
    for (int it = 0; it < 4; ++it) {            // 512 chunks per array
        int idx = it * 128 + tid;
        int row = idx >> 3, c = idx & 7;
        uint32_t so = (uint32_t)(row * PITCHB + c * 16);
        size_t go = (size_t)row * DD + c * 8;
        cpasync16(sb + SM_AH + so, g_Ah + Abase + go);
        cpasync16(sb + SM_AL + so, g_Al + Abase + go);
        cpasync16(sb + SM_BH + so, g_Bh + Bbase + go);
        cpasync16(sb + SM_BL + so, g_Bl + Bbase + go);
    }
    asm volatile("cp.async.commit_group;" ::: "memory");
    asm volatile("cp.async.wait_group 0;" ::: "memory");
    __syncthreads();

    // ---- Per-lane ldmatrix base addresses ----
    const uint32_t a_lane = (uint32_t)((warp_m * 32 + (lid & 15)) * PITCHB +
                                       ((lid >> 4) * 8) * 2);
    const uint32_t b_lane = (uint32_t)((warp_n * 32 + ((lid >> 4) & 1) * 8 + (lid & 7)) * PITCHB +
                                       (((lid >> 3) & 1) * 8) * 2);

    float acc[2][4][4];
    #pragma unroll
    for (int mt = 0; mt < 2; ++mt)
        #pragma unroll
        for (int nt = 0; nt < 4; ++nt)
            #pragma unroll
            for (int r = 0; r < 4; ++r) acc[mt][nt][r] = 0.f;

    const uint32_t pAh = sb + SM_AH + a_lane, pAl = sb + SM_AL + a_lane;
    const uint32_t pBh = sb + SM_BH + b_lane, pBl = sb + SM_BL + b_lane;

    // ---- Mainloop with fragment reuse: Ah*Bh, Al*Bh, Ah*Bl per k-step ----
    #pragma unroll
    for (int ks = 0; ks < 4; ++ks) {
        const uint32_t ko = (uint32_t)(ks * 32);
        uint32_t ah[2][4], al[2][4], bh[2][4], bl[2][4];
        #pragma unroll
        for (int mt = 0; mt < 2; ++mt)
            ldsm4(ah[mt], pAh + (uint32_t)(mt * 16 * PITCHB) + ko);
        #pragma unroll
        for (int nq = 0; nq < 2; ++nq)
            ldsm4(bh[nq], pBh + (uint32_t)(nq * 16 * PITCHB) + ko);
        #pragma unroll
        for (int mt = 0; mt < 2; ++mt)
            #pragma unroll
            for (int nq = 0; nq < 2; ++nq) {
                mma16816(acc[mt][2 * nq],     ah[mt], &bh[nq][0]);
                mma16816(acc[mt][2 * nq + 1], ah[mt], &bh[nq][2]);
            }
        #pragma unroll
        for (int mt = 0; mt < 2; ++mt)
            ldsm4(al[mt], pAl + (uint32_t)(mt * 16 * PITCHB) + ko);
        #pragma unroll
        for (int mt = 0; mt < 2; ++mt)
            #pragma unroll
            for (int nq = 0; nq < 2; ++nq) {
                mma16816(acc[mt][2 * nq],     al[mt], &bh[nq][0]);
                mma16816(acc[mt][2 * nq + 1], al[mt], &bh[nq][2]);
            }
        #pragma unroll
        for (int nq = 0; nq < 2; ++nq)
            ldsm4(bl[nq], pBl + (uint32_t)(nq * 16 * PITCHB) + ko);
        #pragma unroll
        for (int mt = 0; mt < 2; ++mt)
            #pragma unroll
            for (int nq = 0; nq < 2; ++nq) {
                mma16816(acc[mt][2 * nq],     ah[mt], &bl[nq][0]);
                mma16816(acc[mt][2 * nq + 1], ah[mt], &bl[nq][2]);
            }
    }

    // ---- Epilogue: direct register stores (streaming), both batch copies ----
    const float bv = *bias;
    const size_t BST = (size_t)SS * NN * NN;
    const size_t i_base = (size_t)bi * TM + warp_m * 32 + (lid >> 2);
    const size_t j_base = (size_t)bj * TN + warp_n * 32 + (lid & 3) * 2;

    #pragma unroll
    for (int mt = 0; mt < 2; ++mt) {
        #pragma unroll
        for (int nt = 0; nt < 4; ++nt) {
            float2 v0 = make_float2(acc[mt][nt][0] + bv, acc[mt][nt][1] + bv);
            float2 v1 = make_float2(acc[mt][nt][2] + bv, acc[mt][nt][3] + bv);
            float* d = out + ((size_t)s * NN + i_base + mt * 16) * NN + j_base + nt * 8;
            stcs2(d, v0);
            stcs2(d + 8 * NN, v1);
            stcs2(d + BST, v0);
            stcs2(d + BST + 8 * NN, v1);
        }
    }
}

// ---------------------------------------------------------------------------
// Launch
// ---------------------------------------------------------------------------
extern "C" void kernel_launch(void* const* d_in, const int* in_sizes, int n_in,
                              void* d_out, int out_size) {
    const float* x0   = (const float*)d_in[0];  // tensor0 (S,N,D)
    const float* x1   = (const float*)d_in[1];  // tensor1 (S,N,D)
    const float* W    = (const float*)d_in[2];  // kernel (D,D)
    const float* bias = (const float*)d_in[3];  // scalar
    float* out = (float*)d_out;                 // (2,S,N,N)

    prep_kernel<<<384, 256>>>(x0, x1, W);

    cudaFuncSetAttribute(gemm_mma, cudaFuncAttributeMaxDynamicSharedMemorySize, SM_TOTAL);
    dim3 grid(NN / TN, NN / TM, SS);
    gemm_mma<<<grid, 128, SM_TOTAL>>>(bias, out);
}

// round 10
// speedup vs baseline: 1.0921x; 1.0921x over previous
#include <cuda_runtime.h>
#include <cuda_bf16.h>
#include <cstdint>

#define SS 4
#define NN 4096
#define DD 64
#define TM 64     // i rows per CTA
#define TN 128    // j rows per CTA

// Pre-split bf16 hi/lo operand arrays (2 MB each, static — no allocs allowed)
__device__ __nv_bfloat16 g_Ah[(size_t)SS * NN * DD];
__device__ __nv_bfloat16 g_Al[(size_t)SS * NN * DD];
__device__ __nv_bfloat16 g_Bh[(size_t)SS * NN * DD];
__device__ __nv_bfloat16 g_Bl[(size_t)SS * NN * DD];

__device__ __forceinline__ uint32_t pkbf2(float a, float b) {
    __nv_bfloat162 t = __floats2bfloat162_rn(a, b);
    return *(uint32_t*)&t;
}

// ---------------------------------------------------------------------------
// Stage 1 (fused): blocks [0,128):  Q = x0 @ W^T, split -> g_Bh/g_Bl
//                  blocks [128,256): split x1 -> g_Ah/g_Al (8 iters each)
// ---------------------------------------------------------------------------
__global__ __launch_bounds__(256) void prep_kernel(const float* __restrict__ x0,
                                                   const float* __restrict__ x1,
                                                   const float* __restrict__ W) {
    const int tid = threadIdx.x;
    if (blockIdx.x < 128) {
        __shared__ float Ws[DD * DD];
        #pragma unroll
        for (int i = tid; i < DD * DD / 4; i += 256)
            ((float4*)Ws)[i] = ((const float4*)W)[i];
        __syncthreads();

        int gid = blockIdx.x * 256 + tid;      // 0 .. 2*S*N-1
        int row = gid >> 1;
        int half = gid & 1;                    // 32 d-outputs

        const float4* xr = (const float4*)(x0 + (size_t)row * DD);
        float4 x[16];
        #pragma unroll
        for (int e = 0; e < 16; ++e) x[e] = xr[e];

        uint2* qh = (uint2*)(g_Bh + (size_t)row * DD + half * 32);
        uint2* ql = (uint2*)(g_Bl + (size_t)row * DD + half * 32);
        #pragma unroll
        for (int d4 = 0; d4 < 8; ++d4) {
            float r[4];
            #pragma unroll
            for (int dd = 0; dd < 4; ++dd) {
                int d = half * 32 + d4 * 4 + dd;
                const float4* wr = (const float4*)(Ws + d * DD);
                float a0 = 0.f, a1 = 0.f, a2 = 0.f, a3 = 0.f;
                #pragma unroll
                for (int e4 = 0; e4 < 16; e4 += 4) {
                    float4 w0 = wr[e4 + 0], w1 = wr[e4 + 1], w2 = wr[e4 + 2], w3 = wr[e4 + 3];
                    a0 += x[e4 + 0].x * w0.x + x[e4 + 0].y * w0.y + x[e4 + 0].z * w0.z + x[e4 + 0].w * w0.w;
                    a1 += x[e4 + 1].x * w1.x + x[e4 + 1].y * w1.y + x[e4 + 1].z * w1.z + x[e4 + 1].w * w1.w;
                    a2 += x[e4 + 2].x * w2.x + x[e4 + 2].y * w2.y + x[e4 + 2].z * w2.z + x[e4 + 2].w * w2.w;
                    a3 += x[e4 + 3].x * w3.x + x[e4 + 3].y * w3.y + x[e4 + 3].z * w3.z + x[e4 + 3].w * w3.w;
                }
                r[dd] = (a0 + a1) + (a2 + a3);
            }
            float h0 = __bfloat162float(__float2bfloat16(r[0]));
            float h1 = __bfloat162float(__float2bfloat16(r[1]));
            float h2 = __bfloat162float(__float2bfloat16(r[2]));
            float h3 = __bfloat162float(__float2bfloat16(r[3]));
            qh[d4] = make_uint2(pkbf2(h0, h1), pkbf2(h2, h3));
            ql[d4] = make_uint2(pkbf2(r[0] - h0, r[1] - h1), pkbf2(r[2] - h2, r[3] - h3));
        }
    } else {
        // x1 split: 128 blocks over 262144 float4 (8 grid-strided iters)
        int idx = (blockIdx.x - 128) * 256 + tid;
        const float4* src = (const float4*)x1;
        uint2* ah = (uint2*)g_Ah;
        uint2* al = (uint2*)g_Al;
        #pragma unroll
        for (int it = 0; it < 8; ++it) {
            int i = it * 32768 + idx;
            float4 v = src[i];
            float hx = __bfloat162float(__float2bfloat16(v.x));
            float hy = __bfloat162float(__float2bfloat16(v.y));
            float hz = __bfloat162float(__float2bfloat16(v.z));
            float hw = __bfloat162float(__float2bfloat16(v.w));
            ah[i] = make_uint2(pkbf2(hx, hy), pkbf2(hz, hw));
            al[i] = make_uint2(pkbf2(v.x - hx, v.y - hy), pkbf2(v.z - hz, v.w - hw));
        }
    }
}

// ---------------------------------------------------------------------------
// Baseline-PTX tensor core helpers
// ---------------------------------------------------------------------------
__device__ __forceinline__ uint32_t smem_u32(const void* p) {
    uint32_t a;
    asm("{ .reg .u64 t; cvta.to.shared.u64 t, %1; cvt.u32.u64 %0, t; }" : "=r"(a) : "l"(p));
    return a;
}

__device__ __forceinline__ void ldsm4(uint32_t* r, uint32_t addr) {
    asm volatile("ldmatrix.sync.aligned.m8n8.x4.shared.b16 {%0,%1,%2,%3}, [%4];"
                 : "=r"(r[0]), "=r"(r[1]), "=r"(r[2]), "=r"(r[3]) : "r"(addr));
}

__device__ __forceinline__ void mma16816(float* c, const uint32_t* a,
                                         const uint32_t* b) {
    asm volatile(
        "mma.sync.aligned.m16n8k16.row.col.f32.bf16.bf16.f32 "
        "{%0,%1,%2,%3}, {%4,%5,%6,%7}, {%8,%9}, {%0,%1,%2,%3};"
        : "+f"(c[0]), "+f"(c[1]), "+f"(c[2]), "+f"(c[3])
        : "r"(a[0]), "r"(a[1]), "r"(a[2]), "r"(a[3]), "r"(b[0]), "r"(b[1]));
}

__device__ __forceinline__ void stcs2(float* p, float2 v) {
    asm volatile("st.global.cs.v2.f32 [%0], {%1,%2};" :: "l"(p), "f"(v.x), "f"(v.y)
                 : "memory");
}

__device__ __forceinline__ void cpasync16(uint32_t dst, const void* src) {
    asm volatile("cp.async.cg.shared.global [%0], [%1], 16;" :: "r"(dst), "l"(src)
                 : "memory");
}

// SMEM: pitch-144 rows (conflict-free ldmatrix). A: 64 rows, B: 128 rows.
#define PITCHB 144
#define SM_AH  0
#define SM_AL  (TM * PITCHB)                        // 9216
#define SM_BH  (2 * TM * PITCHB)                    // 18432
#define SM_BL  (2 * TM * PITCHB + TN * PITCHB)      // 36864
#define SM_TOTAL (2 * TM * PITCHB + 2 * TN * PITCHB)  // 55296

// ---------------------------------------------------------------------------
// Stage 2: out[s,i,j] = sum_d x1[s,i,d] * Q[s,j,d] via bf16x3 mma.sync.
// 64x128 tile/CTA, 128 threads (4 warps, 2x2), warp tile 32x64, K=64 resident.
// 4 CTAs/SM for cross-CTA phase overlap (proven best: R8).
// ---------------------------------------------------------------------------
__global__ __launch_bounds__(128, 4) void gemm_mma(const float* __restrict__ bias,
                                                   float* __restrict__ out) {
    extern __shared__ char smem[];
    const uint32_t sb = smem_u32(smem);
    const int tid = threadIdx.x, wid = tid >> 5, lid = tid & 31;
    const int s = blockIdx.z, bj = blockIdx.x, bi = blockIdx.y;
    const int warp_m = wid >> 1;   // 0..1, 32 rows
    const int warp_n = wid & 1;    // 0..1, 64 cols

    // ---- Prologue: cp.async the 4 pre-split tiles ----
    const size_t Abase = ((size_t)s * NN + (size_t)bi * TM) * DD;
    const size_t Bbase = ((size_t)s * NN + (size_t)bj * TN) * DD;

    #pragma unroll
    for (int it = 0; it < 4; ++it) {            // A: 512 chunks per array
        int idx = it * 128 + tid;
        int row = idx >> 3, c = idx & 7;
        uint32_t so = (uint32_t)(row * PITCHB + c * 16);
        size_t go = (size_t)row * DD + c * 8;
        cpasync16(sb + SM_AH + so, g_Ah + Abase + go);
        cpasync16(sb + SM_AL + so, g_Al + Abase + go);
    }
    #pragma unroll
    for (int it = 0; it < 8; ++it) {            // B: 1024 chunks per array
        int idx = it * 128 + tid;
        int row = idx >> 3, c = idx & 7;
        uint32_t so = (uint32_t)(row * PITCHB + c * 16);
        size_t go = (size_t)row * DD + c * 8;
        cpasync16(sb + SM_BH + so, g_Bh + Bbase + go);
        cpasync16(sb + SM_BL + so, g_Bl + Bbase + go);
    }
    asm volatile("cp.async.commit_group;" ::: "memory");
    asm volatile("cp.async.wait_group 0;" ::: "memory");
    __syncthreads();

    // ---- Per-lane ldmatrix base addresses ----
    const uint32_t a_lane = (uint32_t)((warp_m * 32 + (lid & 15)) * PITCHB +
                                       ((lid >> 4) * 8) * 2);
    const uint32_t b_lane = (uint32_t)((warp_n * 64 + ((lid >> 4) & 1) * 8 + (lid & 7)) * PITCHB +
                                       (((lid >> 3) & 1) * 8) * 2);

    float acc[2][8][4];
    #pragma unroll
    for (int mt = 0; mt < 2; ++mt)
        #pragma unroll
        for (int nt = 0; nt < 8; ++nt)
            #pragma unroll
            for (int r = 0; r < 4; ++r) acc[mt][nt][r] = 0.f;

    const uint32_t pAh = sb + SM_AH + a_lane, pAl = sb + SM_AL + a_lane;
    const uint32_t pBh = sb + SM_BH + b_lane, pBl = sb + SM_BL + b_lane;

    // ---- Mainloop with fragment reuse: Ah*Bh, Al*Bh, Ah*Bl per k-step ----
    #pragma unroll
    for (int ks = 0; ks < 4; ++ks) {
        const uint32_t ko = (uint32_t)(ks * 32);
        uint32_t ah[2][4], al[2][4], bh[4][4], bl[4][4];
        #pragma unroll
        for (int mt = 0; mt < 2; ++mt)
            ldsm4(ah[mt], pAh + (uint32_t)(mt * 16 * PITCHB) + ko);
        #pragma unroll
        for (int nq = 0; nq < 4; ++nq)
            ldsm4(bh[nq], pBh + (uint32_t)(nq * 16 * PITCHB) + ko);
        #pragma unroll
        for (int mt = 0; mt < 2; ++mt)
            #pragma unroll
            for (int nq = 0; nq < 4; ++nq) {
                mma16816(acc[mt][2 * nq],     ah[mt], &bh[nq][0]);
                mma16816(acc[mt][2 * nq + 1], ah[mt], &bh[nq][2]);
            }
        #pragma unroll
        for (int mt = 0; mt < 2; ++mt)
            ldsm4(al[mt], pAl + (uint32_t)(mt * 16 * PITCHB) + ko);
        #pragma unroll
        for (int mt = 0; mt < 2; ++mt)
            #pragma unroll
            for (int nq = 0; nq < 4; ++nq) {
                mma16816(acc[mt][2 * nq],     al[mt], &bh[nq][0]);
                mma16816(acc[mt][2 * nq + 1], al[mt], &bh[nq][2]);
            }
        #pragma unroll
        for (int nq = 0; nq < 4; ++nq)
            ldsm4(bl[nq], pBl + (uint32_t)(nq * 16 * PITCHB) + ko);
        #pragma unroll
        for (int mt = 0; mt < 2; ++mt)
            #pragma unroll
            for (int nq = 0; nq < 4; ++nq) {
                mma16816(acc[mt][2 * nq],     ah[mt], &bl[nq][0]);
                mma16816(acc[mt][2 * nq + 1], ah[mt], &bl[nq][2]);
            }
    }

    // ---- Epilogue: direct register stores (streaming), both batch copies ----
    const float bv = *bias;
    const size_t BST = (size_t)SS * NN * NN;
    const size_t i_base = (size_t)bi * TM + warp_m * 32 + (lid >> 2);
    const size_t j_base = (size_t)bj * TN + warp_n * 64 + (lid & 3) * 2;

    #pragma unroll
    for (int mt = 0; mt < 2; ++mt) {
        #pragma unroll
        for (int nt = 0; nt < 8; ++nt) {
            float2 v0 = make_float2(acc[mt][nt][0] + bv, acc[mt][nt][1] + bv);
            float2 v1 = make_float2(acc[mt][nt][2] + bv, acc[mt][nt][3] + bv);
            float* d = out + ((size_t)s * NN + i_base + mt * 16) * NN + j_base + nt * 8;
            stcs2(d, v0);
            stcs2(d + 8 * NN, v1);
            stcs2(d + BST, v0);
            stcs2(d + BST + 8 * NN, v1);
        }
    }
}

// ---------------------------------------------------------------------------
// Launch
// ---------------------------------------------------------------------------
extern "C" void kernel_launch(void* const* d_in, const int* in_sizes, int n_in,
                              void* d_out, int out_size) {
    const float* x0   = (const float*)d_in[0];  // tensor0 (S,N,D)
    const float* x1   = (const float*)d_in[1];  // tensor1 (S,N,D)
    const float* W    = (const float*)d_in[2];  // kernel (D,D)
    const float* bias = (const float*)d_in[3];  // scalar
    float* out = (float*)d_out;                 // (2,S,N,N)

    prep_kernel<<<256, 256>>>(x0, x1, W);

    cudaFuncSetAttribute(gemm_mma, cudaFuncAttributeMaxDynamicSharedMemorySize, SM_TOTAL);
    dim3 grid(NN / TN, NN / TM, SS);
    gemm_mma<<<grid, 128, SM_TOTAL>>>(bias, out);
}

// round 11
// speedup vs baseline: 1.1030x; 1.0100x over previous
#include <cuda_runtime.h>
#include <cuda_bf16.h>
#include <cstdint>

#define SS 4
#define NN 4096
#define DD 64
#define TM 64     // i rows per CTA
#define TN 128    // j rows per CTA

// Pre-split bf16 hi/lo Q arrays (2 MB each, static — no allocs allowed)
__device__ __nv_bfloat16 g_Bh[(size_t)SS * NN * DD];
__device__ __nv_bfloat16 g_Bl[(size_t)SS * NN * DD];

__device__ __forceinline__ uint32_t pkbf2(float a, float b) {
    __nv_bfloat162 t = __floats2bfloat162_rn(a, b);
    return *(uint32_t*)&t;
}

// ---------------------------------------------------------------------------
// Stage 1: Q = x0 @ W^T, split -> g_Bh/g_Bl.  2 threads/row, 128 CTAs.
// ---------------------------------------------------------------------------
__global__ __launch_bounds__(256) void prep_kernel(const float* __restrict__ x0,
                                                   const float* __restrict__ W) {
    const int tid = threadIdx.x;
    __shared__ float Ws[DD * DD];
    #pragma unroll
    for (int i = tid; i < DD * DD / 4; i += 256)
        ((float4*)Ws)[i] = ((const float4*)W)[i];
    __syncthreads();

    int gid = blockIdx.x * 256 + tid;      // 0 .. 2*S*N-1
    int row = gid >> 1;
    int half = gid & 1;                    // 32 d-outputs

    const float4* xr = (const float4*)(x0 + (size_t)row * DD);
    float4 x[16];
    #pragma unroll
    for (int e = 0; e < 16; ++e) x[e] = xr[e];

    uint2* qh = (uint2*)(g_Bh + (size_t)row * DD + half * 32);
    uint2* ql = (uint2*)(g_Bl + (size_t)row * DD + half * 32);
    #pragma unroll
    for (int d4 = 0; d4 < 8; ++d4) {
        float r[4];
        #pragma unroll
        for (int dd = 0; dd < 4; ++dd) {
            int d = half * 32 + d4 * 4 + dd;
            const float4* wr = (const float4*)(Ws + d * DD);
            float a0 = 0.f, a1 = 0.f, a2 = 0.f, a3 = 0.f;
            #pragma unroll
            for (int e4 = 0; e4 < 16; e4 += 4) {
                float4 w0 = wr[e4 + 0], w1 = wr[e4 + 1], w2 = wr[e4 + 2], w3 = wr[e4 + 3];
                a0 += x[e4 + 0].x * w0.x + x[e4 + 0].y * w0.y + x[e4 + 0].z * w0.z + x[e4 + 0].w * w0.w;
                a1 += x[e4 + 1].x * w1.x + x[e4 + 1].y * w1.y + x[e4 + 1].z * w1.z + x[e4 + 1].w * w1.w;
                a2 += x[e4 + 2].x * w2.x + x[e4 + 2].y * w2.y + x[e4 + 2].z * w2.z + x[e4 + 2].w * w2.w;
                a3 += x[e4 + 3].x * w3.x + x[e4 + 3].y * w3.y + x[e4 + 3].z * w3.z + x[e4 + 3].w * w3.w;
            }
            r[dd] = (a0 + a1) + (a2 + a3);
        }
        float h0 = __bfloat162float(__float2bfloat16(r[0]));
        float h1 = __bfloat162float(__float2bfloat16(r[1]));
        float h2 = __bfloat162float(__float2bfloat16(r[2]));
        float h3 = __bfloat162float(__float2bfloat16(r[3]));
        qh[d4] = make_uint2(pkbf2(h0, h1), pkbf2(h2, h3));
        ql[d4] = make_uint2(pkbf2(r[0] - h0, r[1] - h1), pkbf2(r[2] - h2, r[3] - h3));
    }
}

// ---------------------------------------------------------------------------
// Baseline-PTX tensor core helpers
// ---------------------------------------------------------------------------
__device__ __forceinline__ uint32_t smem_u32(const void* p) {
    uint32_t a;
    asm("{ .reg .u64 t; cvta.to.shared.u64 t, %1; cvt.u32.u64 %0, t; }" : "=r"(a) : "l"(p));
    return a;
}

__device__ __forceinline__ void ldsm4(uint32_t* r, uint32_t addr) {
    asm volatile("ldmatrix.sync.aligned.m8n8.x4.shared.b16 {%0,%1,%2,%3}, [%4];"
                 : "=r"(r[0]), "=r"(r[1]), "=r"(r[2]), "=r"(r[3]) : "r"(addr));
}

__device__ __forceinline__ void mma16816(float* c, const uint32_t* a,
                                         const uint32_t* b) {
    asm volatile(
        "mma.sync.aligned.m16n8k16.row.col.f32.bf16.bf16.f32 "
        "{%0,%1,%2,%3}, {%4,%5,%6,%7}, {%8,%9}, {%0,%1,%2,%3};"
        : "+f"(c[0]), "+f"(c[1]), "+f"(c[2]), "+f"(c[3])
        : "r"(a[0]), "r"(a[1]), "r"(a[2]), "r"(a[3]), "r"(b[0]), "r"(b[1]));
}

__device__ __forceinline__ void stcs2(float* p, float2 v) {
    asm volatile("st.global.cs.v2.f32 [%0], {%1,%2};" :: "l"(p), "f"(v.x), "f"(v.y)
                 : "memory");
}

__device__ __forceinline__ void cpasync16(uint32_t dst, const void* src) {
    asm volatile("cp.async.cg.shared.global [%0], [%1], 16;" :: "r"(dst), "l"(src)
                 : "memory");
}

// SMEM: pitch-144 rows (conflict-free ldmatrix). A: 64 rows, B: 128 rows.
#define PITCHB 144
#define SM_AH  0
#define SM_AL  (TM * PITCHB)                        // 9216
#define SM_BH  (2 * TM * PITCHB)                    // 18432
#define SM_BL  (2 * TM * PITCHB + TN * PITCHB)      // 36864
#define SM_TOTAL (2 * TM * PITCHB + 2 * TN * PITCHB)  // 55296

// ---------------------------------------------------------------------------
// Stage 2: out[s,i,j] = sum_d x1[s,i,d] * Q[s,j,d] via bf16x3 mma.sync.
// 64x128 tile/CTA, 128 threads (4 warps, 2x2), warp tile 32x64, K=64 resident.
// 4 CTAs/SM. B pre-split (cp.async); A split in-prologue from fp32 x1
// (overlapped with B's async copies; same read bytes as pre-split).
// ---------------------------------------------------------------------------
__global__ __launch_bounds__(128, 4) void gemm_mma(const float* __restrict__ x1,
                                                   const float* __restrict__ bias,
                                                   float* __restrict__ out) {
    extern __shared__ char smem[];
    const uint32_t sb = smem_u32(smem);
    const int tid = threadIdx.x, wid = tid >> 5, lid = tid & 31;
    const int s = blockIdx.z, bj = blockIdx.x, bi = blockIdx.y;
    const int warp_m = wid >> 1;   // 0..1, 32 rows
    const int warp_n = wid & 1;    // 0..1, 64 cols

    // ---- Prologue: B hi/lo via cp.async ----
    const size_t Bbase = ((size_t)s * NN + (size_t)bj * TN) * DD;
    #pragma unroll
    for (int it = 0; it < 8; ++it) {            // B: 1024 chunks per array
        int idx = it * 128 + tid;
        int row = idx >> 3, c = idx & 7;
        uint32_t so = (uint32_t)(row * PITCHB + c * 16);
        size_t go = (size_t)row * DD + c * 8;
        cpasync16(sb + SM_BH + so, g_Bh + Bbase + go);
        cpasync16(sb + SM_BL + so, g_Bl + Bbase + go);
    }
    asm volatile("cp.async.commit_group;" ::: "memory");

    // ---- A: load fp32 x1 tile, split-convert to hi/lo (overlaps B copies) ----
    {
        const float4* Ag = (const float4*)(x1 + ((size_t)s * NN + (size_t)bi * TM) * DD);
        #pragma unroll
        for (int it = 0; it < 8; ++it) {        // 1024 float4 total
            int idx = it * 128 + tid;
            int row = idx >> 4, c4 = idx & 15;
            float4 v = Ag[row * 16 + c4];
            float hx = __bfloat162float(__float2bfloat16(v.x));
            float hy = __bfloat162float(__float2bfloat16(v.y));
            float hz = __bfloat162float(__float2bfloat16(v.z));
            float hw = __bfloat162float(__float2bfloat16(v.w));
            uint32_t off = (uint32_t)(row * PITCHB + c4 * 8);
            *(uint2*)(smem + SM_AH + off) = make_uint2(pkbf2(hx, hy), pkbf2(hz, hw));
            *(uint2*)(smem + SM_AL + off) =
                make_uint2(pkbf2(v.x - hx, v.y - hy), pkbf2(v.z - hz, v.w - hw));
        }
    }
    asm volatile("cp.async.wait_group 0;" ::: "memory");
    __syncthreads();

    // ---- Per-lane ldmatrix base addresses ----
    const uint32_t a_lane = (uint32_t)((warp_m * 32 + (lid & 15)) * PITCHB +
                                       ((lid >> 4) * 8) * 2);
    const uint32_t b_lane = (uint32_t)((warp_n * 64 + ((lid >> 4) & 1) * 8 + (lid & 7)) * PITCHB +
                                       (((lid >> 3) & 1) * 8) * 2);

    float acc[2][8][4];
    #pragma unroll
    for (int mt = 0; mt < 2; ++mt)
        #pragma unroll
        for (int nt = 0; nt < 8; ++nt)
            #pragma unroll
            for (int r = 0; r < 4; ++r) acc[mt][nt][r] = 0.f;

    const uint32_t pAh = sb + SM_AH + a_lane, pAl = sb + SM_AL + a_lane;
    const uint32_t pBh = sb + SM_BH + b_lane, pBl = sb + SM_BL + b_lane;

    // ---- Mainloop with fragment reuse: Ah*Bh, Al*Bh, Ah*Bl per k-step ----
    #pragma unroll
    for (int ks = 0; ks < 4; ++ks) {
        const uint32_t ko = (uint32_t)(ks * 32);
        uint32_t ah[2][4], al[2][4], bh[4][4], bl[4][4];
        #pragma unroll
        for (int mt = 0; mt < 2; ++mt)
            ldsm4(ah[mt], pAh + (uint32_t)(mt * 16 * PITCHB) + ko);
        #pragma unroll
        for (int nq = 0; nq < 4; ++nq)
            ldsm4(bh[nq], pBh + (uint32_t)(nq * 16 * PITCHB) + ko);
        #pragma unroll
        for (int mt = 0; mt < 2; ++mt)
            #pragma unroll
            for (int nq = 0; nq < 4; ++nq) {
                mma16816(acc[mt][2 * nq],     ah[mt], &bh[nq][0]);
                mma16816(acc[mt][2 * nq + 1], ah[mt], &bh[nq][2]);
            }
        #pragma unroll
        for (int mt = 0; mt < 2; ++mt)
            ldsm4(al[mt], pAl + (uint32_t)(mt * 16 * PITCHB) + ko);
        #pragma unroll
        for (int mt = 0; mt < 2; ++mt)
            #pragma unroll
            for (int nq = 0; nq < 4; ++nq) {
                mma16816(acc[mt][2 * nq],     al[mt], &bh[nq][0]);
                mma16816(acc[mt][2 * nq + 1], al[mt], &bh[nq][2]);
            }
        #pragma unroll
        for (int nq = 0; nq < 4; ++nq)
            ldsm4(bl[nq], pBl + (uint32_t)(nq * 16 * PITCHB) + ko);
        #pragma unroll
        for (int mt = 0; mt < 2; ++mt)
            #pragma unroll
            for (int nq = 0; nq < 4; ++nq) {
                mma16816(acc[mt][2 * nq],     ah[mt], &bl[nq][0]);
                mma16816(acc[mt][2 * nq + 1], ah[mt], &bl[nq][2]);
            }
    }

    // ---- Epilogue: direct register stores (streaming), both batch copies ----
    const float bv = *bias;
    const size_t BST = (size_t)SS * NN * NN;
    const size_t i_base = (size_t)bi * TM + warp_m * 32 + (lid >> 2);
    const size_t j_base = (size_t)bj * TN + warp_n * 64 + (lid & 3) * 2;

    #pragma unroll
    for (int mt = 0; mt < 2; ++mt) {
        #pragma unroll
        for (int nt = 0; nt < 8; ++nt) {
            float2 v0 = make_float2(acc[mt][nt][0] + bv, acc[mt][nt][1] + bv);
            float2 v1 = make_float2(acc[mt][nt][2] + bv, acc[mt][nt][3] + bv);
            float* d = out + ((size_t)s * NN + i_base + mt * 16) * NN + j_base + nt * 8;
            stcs2(d, v0);
            stcs2(d + 8 * NN, v1);
            stcs2(d + BST, v0);
            stcs2(d + BST + 8 * NN, v1);
        }
    }
}

// ---------------------------------------------------------------------------
// Launch
// ---------------------------------------------------------------------------
extern "C" void kernel_launch(void* const* d_in, const int* in_sizes, int n_in,
                              void* d_out, int out_size) {
    const float* x0   = (const float*)d_in[0];  // tensor0 (S,N,D)
    const float* x1   = (const float*)d_in[1];  // tensor1 (S,N,D)
    const float* W    = (const float*)d_in[2];  // kernel (D,D)
    const float* bias = (const float*)d_in[3];  // scalar
    float* out = (float*)d_out;                 // (2,S,N,N)

    prep_kernel<<<128, 256>>>(x0, W);

    cudaFuncSetAttribute(gemm_mma, cudaFuncAttributeMaxDynamicSharedMemorySize, SM_TOTAL);
    dim3 grid(NN / TN, NN / TM, SS);
    gemm_mma<<<grid, 128, SM_TOTAL>>>(x1, bias, out);
}

// round 12
// speedup vs baseline: 1.1635x; 1.0548x over previous
#include <cuda_runtime.h>
#include <cuda_bf16.h>
#include <cstdint>

#define SS 4
#define NN 4096
#define DD 64
#define TM 64     // i rows per CTA (stage 2)
#define TN 128    // j rows per CTA (stage 2)

// Pre-split bf16 hi/lo Q arrays (2 MB each, static — no allocs allowed)
__device__ __nv_bfloat16 g_Bh[(size_t)SS * NN * DD];
__device__ __nv_bfloat16 g_Bl[(size_t)SS * NN * DD];

__device__ __forceinline__ uint32_t pkbf2(float a, float b) {
    __nv_bfloat162 t = __floats2bfloat162_rn(a, b);
    return *(uint32_t*)&t;
}

// ---------------------------------------------------------------------------
// Baseline-PTX tensor core helpers
// ---------------------------------------------------------------------------
__device__ __forceinline__ uint32_t smem_u32(const void* p) {
    uint32_t a;
    asm("{ .reg .u64 t; cvta.to.shared.u64 t, %1; cvt.u32.u64 %0, t; }" : "=r"(a) : "l"(p));
    return a;
}

__device__ __forceinline__ void ldsm4(uint32_t* r, uint32_t addr) {
    asm volatile("ldmatrix.sync.aligned.m8n8.x4.shared.b16 {%0,%1,%2,%3}, [%4];"
                 : "=r"(r[0]), "=r"(r[1]), "=r"(r[2]), "=r"(r[3]) : "r"(addr));
}

__device__ __forceinline__ void mma16816(float* c, const uint32_t* a,
                                         const uint32_t* b) {
    asm volatile(
        "mma.sync.aligned.m16n8k16.row.col.f32.bf16.bf16.f32 "
        "{%0,%1,%2,%3}, {%4,%5,%6,%7}, {%8,%9}, {%0,%1,%2,%3};"
        : "+f"(c[0]), "+f"(c[1]), "+f"(c[2]), "+f"(c[3])
        : "r"(a[0]), "r"(a[1]), "r"(a[2]), "r"(a[3]), "r"(b[0]), "r"(b[1]));
}

__device__ __forceinline__ void stcs2(float* p, float2 v) {
    asm volatile("st.global.cs.v2.f32 [%0], {%1,%2};" :: "l"(p), "f"(v.x), "f"(v.y)
                 : "memory");
}

__device__ __forceinline__ void cpasync16(uint32_t dst, const void* src) {
    asm volatile("cp.async.cg.shared.global [%0], [%1], 16;" :: "r"(dst), "l"(src)
                 : "memory");
}

#define PITCHB 144   // bf16 row pitch in bytes: conflict-free ldmatrix

// ---------------------------------------------------------------------------
// Stage 1: Q = x0 @ W^T via the SAME bf16x3 mma machinery.
// M=16384, N=64, K=64. 128 CTAs x 128 threads; CTA tile 128 rows x 64.
// Output split to hi/lo and stored straight from accumulators.
// ---------------------------------------------------------------------------
#define QA_H 0
#define QA_L (128 * PITCHB)              // 18432
#define QW_H (2 * 128 * PITCHB)          // 36864
#define QW_L (2 * 128 * PITCHB + 64 * PITCHB)  // 46080
#define QSM_TOTAL (2 * 128 * PITCHB + 2 * 64 * PITCHB)  // 55296

__global__ __launch_bounds__(128, 4) void prep_mma(const float* __restrict__ x0,
                                                   const float* __restrict__ W) {
    extern __shared__ char smem[];
    const uint32_t sb = smem_u32(smem);
    const int tid = threadIdx.x, wid = tid >> 5, lid = tid & 31;

    // ---- Split-convert x0 tile (128 rows) and W (64 rows) to smem hi/lo ----
    const float4* Ag = (const float4*)(x0 + (size_t)blockIdx.x * 128 * DD);
    #pragma unroll
    for (int it = 0; it < 16; ++it) {           // 2048 float4
        int idx = it * 128 + tid;
        int row = idx >> 4, c4 = idx & 15;
        float4 v = Ag[idx];
        float hx = __bfloat162float(__float2bfloat16(v.x));
        float hy = __bfloat162float(__float2bfloat16(v.y));
        float hz = __bfloat162float(__float2bfloat16(v.z));
        float hw = __bfloat162float(__float2bfloat16(v.w));
        uint32_t off = (uint32_t)(row * PITCHB + c4 * 8);
        *(uint2*)(smem + QA_H + off) = make_uint2(pkbf2(hx, hy), pkbf2(hz, hw));
        *(uint2*)(smem + QA_L + off) =
            make_uint2(pkbf2(v.x - hx, v.y - hy), pkbf2(v.z - hz, v.w - hw));
    }
    const float4* Wg = (const float4*)W;
    #pragma unroll
    for (int it = 0; it < 8; ++it) {            // 1024 float4
        int idx = it * 128 + tid;
        int row = idx >> 4, c4 = idx & 15;
        float4 v = Wg[idx];
        float hx = __bfloat162float(__float2bfloat16(v.x));
        float hy = __bfloat162float(__float2bfloat16(v.y));
        float hz = __bfloat162float(__float2bfloat16(v.z));
        float hw = __bfloat162float(__float2bfloat16(v.w));
        uint32_t off = (uint32_t)(row * PITCHB + c4 * 8);
        *(uint2*)(smem + QW_H + off) = make_uint2(pkbf2(hx, hy), pkbf2(hz, hw));
        *(uint2*)(smem + QW_L + off) =
            make_uint2(pkbf2(v.x - hx, v.y - hy), pkbf2(v.z - hz, v.w - hw));
    }
    __syncthreads();

    // ---- Mainloop (identical structure to stage 2): warp tile 32 x 64 ----
    const uint32_t a_lane = (uint32_t)((wid * 32 + (lid & 15)) * PITCHB +
                                       ((lid >> 4) * 8) * 2);
    const uint32_t b_lane = (uint32_t)((((lid >> 4) & 1) * 8 + (lid & 7)) * PITCHB +
                                       (((lid >> 3) & 1) * 8) * 2);

    float acc[2][8][4];
    #pragma unroll
    for (int mt = 0; mt < 2; ++mt)
        #pragma unroll
        for (int nt = 0; nt < 8; ++nt)
            #pragma unroll
            for (int r = 0; r < 4; ++r) acc[mt][nt][r] = 0.f;

    const uint32_t pAh = sb + QA_H + a_lane, pAl = sb + QA_L + a_lane;
    const uint32_t pWh = sb + QW_H + b_lane, pWl = sb + QW_L + b_lane;

    #pragma unroll
    for (int ks = 0; ks < 4; ++ks) {
        const uint32_t ko = (uint32_t)(ks * 32);
        uint32_t ah[2][4], al[2][4], bh[4][4], bl[4][4];
        #pragma unroll
        for (int mt = 0; mt < 2; ++mt)
            ldsm4(ah[mt], pAh + (uint32_t)(mt * 16 * PITCHB) + ko);
        #pragma unroll
        for (int nq = 0; nq < 4; ++nq)
            ldsm4(bh[nq], pWh + (uint32_t)(nq * 16 * PITCHB) + ko);
        #pragma unroll
        for (int mt = 0; mt < 2; ++mt)
            #pragma unroll
            for (int nq = 0; nq < 4; ++nq) {
                mma16816(acc[mt][2 * nq],     ah[mt], &bh[nq][0]);
                mma16816(acc[mt][2 * nq + 1], ah[mt], &bh[nq][2]);
            }
        #pragma unroll
        for (int mt = 0; mt < 2; ++mt)
            ldsm4(al[mt], pAl + (uint32_t)(mt * 16 * PITCHB) + ko);
        #pragma unroll
        for (int mt = 0; mt < 2; ++mt)
            #pragma unroll
            for (int nq = 0; nq < 4; ++nq) {
                mma16816(acc[mt][2 * nq],     al[mt], &bh[nq][0]);
                mma16816(acc[mt][2 * nq + 1], al[mt], &bh[nq][2]);
            }
        #pragma unroll
        for (int nq = 0; nq < 4; ++nq)
            ldsm4(bl[nq], pWl + (uint32_t)(nq * 16 * PITCHB) + ko);
        #pragma unroll
        for (int mt = 0; mt < 2; ++mt)
            #pragma unroll
            for (int nq = 0; nq < 4; ++nq) {
                mma16816(acc[mt][2 * nq],     ah[mt], &bl[nq][0]);
                mma16816(acc[mt][2 * nq + 1], ah[mt], &bl[nq][2]);
            }
    }

    // ---- Epilogue: split Q to hi/lo in registers, store bf16x2 words ----
    const size_t row0 = (size_t)blockIdx.x * 128 + wid * 32 + (lid >> 2);
    const int col0 = (lid & 3) * 2;
    #pragma unroll
    for (int mt = 0; mt < 2; ++mt) {
        #pragma unroll
        for (int nt = 0; nt < 8; ++nt) {
            float v0 = acc[mt][nt][0], v1 = acc[mt][nt][1];
            float v2 = acc[mt][nt][2], v3 = acc[mt][nt][3];
            float h0 = __bfloat162float(__float2bfloat16(v0));
            float h1 = __bfloat162float(__float2bfloat16(v1));
            float h2 = __bfloat162float(__float2bfloat16(v2));
            float h3 = __bfloat162float(__float2bfloat16(v3));
            size_t ia = (row0 + mt * 16) * DD + col0 + nt * 8;
            size_t ib = (row0 + mt * 16 + 8) * DD + col0 + nt * 8;
            *(uint32_t*)(g_Bh + ia) = pkbf2(h0, h1);
            *(uint32_t*)(g_Bl + ia) = pkbf2(v0 - h0, v1 - h1);
            *(uint32_t*)(g_Bh + ib) = pkbf2(h2, h3);
            *(uint32_t*)(g_Bl + ib) = pkbf2(v2 - h2, v3 - h3);
        }
    }
}

// SMEM (stage 2): pitch-144 rows. A: 64 rows, B: 128 rows.
#define SM_AH  0
#define SM_AL  (TM * PITCHB)                        // 9216
#define SM_BH  (2 * TM * PITCHB)                    // 18432
#define SM_BL  (2 * TM * PITCHB + TN * PITCHB)      // 36864
#define SM_TOTAL (2 * TM * PITCHB + 2 * TN * PITCHB)  // 55296

// ---------------------------------------------------------------------------
// Stage 2 (unchanged from R11, proven 125.2us): out = x1 @ Q^T, bf16x3 mma.
// ---------------------------------------------------------------------------
__global__ __launch_bounds__(128, 4) void gemm_mma(const float* __restrict__ x1,
                                                   const float* __restrict__ bias,
                                                   float* __restrict__ out) {
    extern __shared__ char smem[];
    const uint32_t sb = smem_u32(smem);
    const int tid = threadIdx.x, wid = tid >> 5, lid = tid & 31;
    const int s = blockIdx.z, bj = blockIdx.x, bi = blockIdx.y;
    const int warp_m = wid >> 1;   // 0..1, 32 rows
    const int warp_n = wid & 1;    // 0..1, 64 cols

    // ---- Prologue: B hi/lo via cp.async ----
    const size_t Bbase = ((size_t)s * NN + (size_t)bj * TN) * DD;
    #pragma unroll
    for (int it = 0; it < 8; ++it) {
        int idx = it * 128 + tid;
        int row = idx >> 3, c = idx & 7;
        uint32_t so = (uint32_t)(row * PITCHB + c * 16);
        size_t go = (size_t)row * DD + c * 8;
        cpasync16(sb + SM_BH + so, g_Bh + Bbase + go);
        cpasync16(sb + SM_BL + so, g_Bl + Bbase + go);
    }
    asm volatile("cp.async.commit_group;" ::: "memory");

    // ---- A: load fp32 x1 tile, split-convert to hi/lo (overlaps B copies) ----
    {
        const float4* Ag = (const float4*)(x1 + ((size_t)s * NN + (size_t)bi * TM) * DD);
        #pragma unroll
        for (int it = 0; it < 8; ++it) {
            int idx = it * 128 + tid;
            int row = idx >> 4, c4 = idx & 15;
            float4 v = Ag[row * 16 + c4];
            float hx = __bfloat162float(__float2bfloat16(v.x));
            float hy = __bfloat162float(__float2bfloat16(v.y));
            float hz = __bfloat162float(__float2bfloat16(v.z));
            float hw = __bfloat162float(__float2bfloat16(v.w));
            uint32_t off = (uint32_t)(row * PITCHB + c4 * 8);
            *(uint2*)(smem + SM_AH + off) = make_uint2(pkbf2(hx, hy), pkbf2(hz, hw));
            *(uint2*)(smem + SM_AL + off) =
                make_uint2(pkbf2(v.x - hx, v.y - hy), pkbf2(v.z - hz, v.w - hw));
        }
    }
    asm volatile("cp.async.wait_group 0;" ::: "memory");
    __syncthreads();

    // ---- Per-lane ldmatrix base addresses ----
    const uint32_t a_lane = (uint32_t)((warp_m * 32 + (lid & 15)) * PITCHB +
                                       ((lid >> 4) * 8) * 2);
    const uint32_t b_lane = (uint32_t)((warp_n * 64 + ((lid >> 4) & 1) * 8 + (lid & 7)) * PITCHB +
                                       (((lid >> 3) & 1) * 8) * 2);

    float acc[2][8][4];
    #pragma unroll
    for (int mt = 0; mt < 2; ++mt)
        #pragma unroll
        for (int nt = 0; nt < 8; ++nt)
            #pragma unroll
            for (int r = 0; r < 4; ++r) acc[mt][nt][r] = 0.f;

    const uint32_t pAh = sb + SM_AH + a_lane, pAl = sb + SM_AL + a_lane;
    const uint32_t pBh = sb + SM_BH + b_lane, pBl = sb + SM_BL + b_lane;

    #pragma unroll
    for (int ks = 0; ks < 4; ++ks) {
        const uint32_t ko = (uint32_t)(ks * 32);
        uint32_t ah[2][4], al[2][4], bh[4][4], bl[4][4];
        #pragma unroll
        for (int mt = 0; mt < 2; ++mt)
            ldsm4(ah[mt], pAh + (uint32_t)(mt * 16 * PITCHB) + ko);
        #pragma unroll
        for (int nq = 0; nq < 4; ++nq)
            ldsm4(bh[nq], pBh + (uint32_t)(nq * 16 * PITCHB) + ko);
        #pragma unroll
        for (int mt = 0; mt < 2; ++mt)
            #pragma unroll
            for (int nq = 0; nq < 4; ++nq) {
                mma16816(acc[mt][2 * nq],     ah[mt], &bh[nq][0]);
                mma16816(acc[mt][2 * nq + 1], ah[mt], &bh[nq][2]);
            }
        #pragma unroll
        for (int mt = 0; mt < 2; ++mt)
            ldsm4(al[mt], pAl + (uint32_t)(mt * 16 * PITCHB) + ko);
        #pragma unroll
        for (int mt = 0; mt < 2; ++mt)
            #pragma unroll
            for (int nq = 0; nq < 4; ++nq) {
                mma16816(acc[mt][2 * nq],     al[mt], &bh[nq][0]);
                mma16816(acc[mt][2 * nq + 1], al[mt], &bh[nq][2]);
            }
        #pragma unroll
        for (int nq = 0; nq < 4; ++nq)
            ldsm4(bl[nq], pBl + (uint32_t)(nq * 16 * PITCHB) + ko);
        #pragma unroll
        for (int mt = 0; mt < 2; ++mt)
            #pragma unroll
            for (int nq = 0; nq < 4; ++nq) {
                mma16816(acc[mt][2 * nq],     ah[mt], &bl[nq][0]);
                mma16816(acc[mt][2 * nq + 1], ah[mt], &bl[nq][2]);
            }
    }

    // ---- Epilogue: direct register stores (streaming), both batch copies ----
    const float bv = *bias;
    const size_t BST = (size_t)SS * NN * NN;
    const size_t i_base = (size_t)bi * TM + warp_m * 32 + (lid >> 2);
    const size_t j_base = (size_t)bj * TN + warp_n * 64 + (lid & 3) * 2;

    #pragma unroll
    for (int mt = 0; mt < 2; ++mt) {
        #pragma unroll
        for (int nt = 0; nt < 8; ++nt) {
            float2 v0 = make_float2(acc[mt][nt][0] + bv, acc[mt][nt][1] + bv);
            float2 v1 = make_float2(acc[mt][nt][2] + bv, acc[mt][nt][3] + bv);
            float* d = out + ((size_t)s * NN + i_base + mt * 16) * NN + j_base + nt * 8;
            stcs2(d, v0);
            stcs2(d + 8 * NN, v1);
            stcs2(d + BST, v0);
            stcs2(d + BST + 8 * NN, v1);
        }
    }
}

// ---------------------------------------------------------------------------
// Launch
// ---------------------------------------------------------------------------
extern "C" void kernel_launch(void* const* d_in, const int* in_sizes, int n_in,
                              void* d_out, int out_size) {
    const float* x0   = (const float*)d_in[0];  // tensor0 (S,N,D)
    const float* x1   = (const float*)d_in[1];  // tensor1 (S,N,D)
    const float* W    = (const float*)d_in[2];  // kernel (D,D)
    const float* bias = (const float*)d_in[3];  // scalar
    float* out = (float*)d_out;                 // (2,S,N,N)

    cudaFuncSetAttribute(prep_mma, cudaFuncAttributeMaxDynamicSharedMemorySize, QSM_TOTAL);
    prep_mma<<<(SS * NN) / 128, 128, QSM_TOTAL>>>(x0, W);

    cudaFuncSetAttribute(gemm_mma, cudaFuncAttributeMaxDynamicSharedMemorySize, SM_TOTAL);
    dim3 grid(NN / TN, NN / TM, SS);
    gemm_mma<<<grid, 128, SM_TOTAL>>>(x1, bias, out);
}

// round 13
// speedup vs baseline: 1.1919x; 1.0244x over previous
#include <cuda_runtime.h>
#include <cuda_bf16.h>
#include <cstdint>

#define SS 4
#define NN 4096
#define DD 64
#define TM 64     // i rows per CTA (stage 2)
#define TN 128    // j rows per CTA (stage 2)

// Pre-split bf16 hi/lo Q arrays (2 MB each, static — no allocs allowed)
__device__ __nv_bfloat16 g_Bh[(size_t)SS * NN * DD];
__device__ __nv_bfloat16 g_Bl[(size_t)SS * NN * DD];

__device__ __forceinline__ uint32_t pkbf2(float a, float b) {
    __nv_bfloat162 t = __floats2bfloat162_rn(a, b);
    return *(uint32_t*)&t;
}

// ---------------------------------------------------------------------------
// Baseline-PTX tensor core helpers
// ---------------------------------------------------------------------------
__device__ __forceinline__ uint32_t smem_u32(const void* p) {
    uint32_t a;
    asm("{ .reg .u64 t; cvta.to.shared.u64 t, %1; cvt.u32.u64 %0, t; }" : "=r"(a) : "l"(p));
    return a;
}

__device__ __forceinline__ void ldsm4(uint32_t* r, uint32_t addr) {
    asm volatile("ldmatrix.sync.aligned.m8n8.x4.shared.b16 {%0,%1,%2,%3}, [%4];"
                 : "=r"(r[0]), "=r"(r[1]), "=r"(r[2]), "=r"(r[3]) : "r"(addr));
}

__device__ __forceinline__ void mma16816(float* c, const uint32_t* a,
                                         const uint32_t* b) {
    asm volatile(
        "mma.sync.aligned.m16n8k16.row.col.f32.bf16.bf16.f32 "
        "{%0,%1,%2,%3}, {%4,%5,%6,%7}, {%8,%9}, {%0,%1,%2,%3};"
        : "+f"(c[0]), "+f"(c[1]), "+f"(c[2]), "+f"(c[3])
        : "r"(a[0]), "r"(a[1]), "r"(a[2]), "r"(a[3]), "r"(b[0]), "r"(b[1]));
}

__device__ __forceinline__ void stcs2(float* p, float2 v) {
    asm volatile("st.global.cs.v2.f32 [%0], {%1,%2};" :: "l"(p), "f"(v.x), "f"(v.y)
                 : "memory");
}

__device__ __forceinline__ void cpasync16(uint32_t dst, const void* src) {
    asm volatile("cp.async.cg.shared.global [%0], [%1], 16;" :: "r"(dst), "l"(src)
                 : "memory");
}

#define PITCHB 144   // bf16 row pitch in bytes: conflict-free ldmatrix

// ---------------------------------------------------------------------------
// Stage 1: Q = x0 @ W^T via bf16x3 mma (proven R12). Signals PDL dependents.
// ---------------------------------------------------------------------------
#define QA_H 0
#define QA_L (128 * PITCHB)              // 18432
#define QW_H (2 * 128 * PITCHB)          // 36864
#define QW_L (2 * 128 * PITCHB + 64 * PITCHB)  // 46080
#define QSM_TOTAL (2 * 128 * PITCHB + 2 * 64 * PITCHB)  // 55296

__global__ __launch_bounds__(128, 4) void prep_mma(const float* __restrict__ x0,
                                                   const float* __restrict__ W) {
    extern __shared__ char smem[];
    const uint32_t sb = smem_u32(smem);
    const int tid = threadIdx.x, wid = tid >> 5, lid = tid & 31;

    // ---- Split-convert x0 tile (128 rows) and W (64 rows) to smem hi/lo ----
    const float4* Ag = (const float4*)(x0 + (size_t)blockIdx.x * 128 * DD);
    #pragma unroll
    for (int it = 0; it < 16; ++it) {           // 2048 float4
        int idx = it * 128 + tid;
        int row = idx >> 4, c4 = idx & 15;
        float4 v = Ag[idx];
        float hx = __bfloat162float(__float2bfloat16(v.x));
        float hy = __bfloat162float(__float2bfloat16(v.y));
        float hz = __bfloat162float(__float2bfloat16(v.z));
        float hw = __bfloat162float(__float2bfloat16(v.w));
        uint32_t off = (uint32_t)(row * PITCHB + c4 * 8);
        *(uint2*)(smem + QA_H + off) = make_uint2(pkbf2(hx, hy), pkbf2(hz, hw));
        *(uint2*)(smem + QA_L + off) =
            make_uint2(pkbf2(v.x - hx, v.y - hy), pkbf2(v.z - hz, v.w - hw));
    }
    const float4* Wg = (const float4*)W;
    #pragma unroll
    for (int it = 0; it < 8; ++it) {            // 1024 float4
        int idx = it * 128 + tid;
        int row = idx >> 4, c4 = idx & 15;
        float4 v = Wg[idx];
        float hx = __bfloat162float(__float2bfloat16(v.x));
        float hy = __bfloat162float(__float2bfloat16(v.y));
        float hz = __bfloat162float(__float2bfloat16(v.z));
        float hw = __bfloat162float(__float2bfloat16(v.w));
        uint32_t off = (uint32_t)(row * PITCHB + c4 * 8);
        *(uint2*)(smem + QW_H + off) = make_uint2(pkbf2(hx, hy), pkbf2(hz, hw));
        *(uint2*)(smem + QW_L + off) =
            make_uint2(pkbf2(v.x - hx, v.y - hy), pkbf2(v.z - hz, v.w - hw));
    }
    __syncthreads();

    // ---- Mainloop: warp tile 32 x 64 ----
    const uint32_t a_lane = (uint32_t)((wid * 32 + (lid & 15)) * PITCHB +
                                       ((lid >> 4) * 8) * 2);
    const uint32_t b_lane = (uint32_t)((((lid >> 4) & 1) * 8 + (lid & 7)) * PITCHB +
                                       (((lid >> 3) & 1) * 8) * 2);

    float acc[2][8][4];
    #pragma unroll
    for (int mt = 0; mt < 2; ++mt)
        #pragma unroll
        for (int nt = 0; nt < 8; ++nt)
            #pragma unroll
            for (int r = 0; r < 4; ++r) acc[mt][nt][r] = 0.f;

    const uint32_t pAh = sb + QA_H + a_lane, pAl = sb + QA_L + a_lane;
    const uint32_t pWh = sb + QW_H + b_lane, pWl = sb + QW_L + b_lane;

    #pragma unroll
    for (int ks = 0; ks < 4; ++ks) {
        const uint32_t ko = (uint32_t)(ks * 32);
        uint32_t ah[2][4], al[2][4], bh[4][4], bl[4][4];
        #pragma unroll
        for (int mt = 0; mt < 2; ++mt)
            ldsm4(ah[mt], pAh + (uint32_t)(mt * 16 * PITCHB) + ko);
        #pragma unroll
        for (int nq = 0; nq < 4; ++nq)
            ldsm4(bh[nq], pWh + (uint32_t)(nq * 16 * PITCHB) + ko);
        #pragma unroll
        for (int mt = 0; mt < 2; ++mt)
            #pragma unroll
            for (int nq = 0; nq < 4; ++nq) {
                mma16816(acc[mt][2 * nq],     ah[mt], &bh[nq][0]);
                mma16816(acc[mt][2 * nq + 1], ah[mt], &bh[nq][2]);
            }
        #pragma unroll
        for (int mt = 0; mt < 2; ++mt)
            ldsm4(al[mt], pAl + (uint32_t)(mt * 16 * PITCHB) + ko);
        #pragma unroll
        for (int mt = 0; mt < 2; ++mt)
            #pragma unroll
            for (int nq = 0; nq < 4; ++nq) {
                mma16816(acc[mt][2 * nq],     al[mt], &bh[nq][0]);
                mma16816(acc[mt][2 * nq + 1], al[mt], &bh[nq][2]);
            }
        #pragma unroll
        for (int nq = 0; nq < 4; ++nq)
            ldsm4(bl[nq], pWl + (uint32_t)(nq * 16 * PITCHB) + ko);
        #pragma unroll
        for (int mt = 0; mt < 2; ++mt)
            #pragma unroll
            for (int nq = 0; nq < 4; ++nq) {
                mma16816(acc[mt][2 * nq],     ah[mt], &bl[nq][0]);
                mma16816(acc[mt][2 * nq + 1], ah[mt], &bl[nq][2]);
            }
    }

    // ---- Epilogue: split Q to hi/lo in registers, store bf16x2 words ----
    const size_t row0 = (size_t)blockIdx.x * 128 + wid * 32 + (lid >> 2);
    const int col0 = (lid & 3) * 2;
    #pragma unroll
    for (int mt = 0; mt < 2; ++mt) {
        #pragma unroll
        for (int nt = 0; nt < 8; ++nt) {
            float v0 = acc[mt][nt][0], v1 = acc[mt][nt][1];
            float v2 = acc[mt][nt][2], v3 = acc[mt][nt][3];
            float h0 = __bfloat162float(__float2bfloat16(v0));
            float h1 = __bfloat162float(__float2bfloat16(v1));
            float h2 = __bfloat162float(__float2bfloat16(v2));
            float h3 = __bfloat162float(__float2bfloat16(v3));
            size_t ia = (row0 + mt * 16) * DD + col0 + nt * 8;
            size_t ib = (row0 + mt * 16 + 8) * DD + col0 + nt * 8;
            *(uint32_t*)(g_Bh + ia) = pkbf2(h0, h1);
            *(uint32_t*)(g_Bl + ia) = pkbf2(v0 - h0, v1 - h1);
            *(uint32_t*)(g_Bh + ib) = pkbf2(h2, h3);
            *(uint32_t*)(g_Bl + ib) = pkbf2(v2 - h2, v3 - h3);
        }
    }

    // PDL: Q stores done — let dependent gemm CTAs launch.
    asm volatile("griddepcontrol.launch_dependents;" ::: "memory");
}

// SMEM (stage 2): pitch-144 rows. A: 64 rows, B: 128 rows.
#define SM_AH  0
#define SM_AL  (TM * PITCHB)                        // 9216
#define SM_BH  (2 * TM * PITCHB)                    // 18432
#define SM_BL  (2 * TM * PITCHB + TN * PITCHB)      // 36864
#define SM_TOTAL (2 * TM * PITCHB + 2 * TN * PITCHB)  // 55296

// ---------------------------------------------------------------------------
// Stage 2: out = x1 @ Q^T, bf16x3 mma (mainloop/epilogue unchanged, proven).
// PDL: Q-independent A-conversion runs BEFORE griddepcontrol.wait.
// ---------------------------------------------------------------------------
__global__ __launch_bounds__(128, 4) void gemm_mma(const float* __restrict__ x1,
                                                   const float* __restrict__ bias,
                                                   float* __restrict__ out) {
    extern __shared__ char smem[];
    const uint32_t sb = smem_u32(smem);
    const int tid = threadIdx.x, wid = tid >> 5, lid = tid & 31;
    const int s = blockIdx.z, bj = blockIdx.x, bi = blockIdx.y;
    const int warp_m = wid >> 1;   // 0..1, 32 rows
    const int warp_n = wid & 1;    // 0..1, 64 cols

    // ---- A first (independent of prep): load fp32 x1 tile, split to hi/lo ----
    {
        const float4* Ag = (const float4*)(x1 + ((size_t)s * NN + (size_t)bi * TM) * DD);
        #pragma unroll
        for (int it = 0; it < 8; ++it) {
            int idx = it * 128 + tid;
            int row = idx >> 4, c4 = idx & 15;
            float4 v = Ag[row * 16 + c4];
            float hx = __bfloat162float(__float2bfloat16(v.x));
            float hy = __bfloat162float(__float2bfloat16(v.y));
            float hz = __bfloat162float(__float2bfloat16(v.z));
            float hw = __bfloat162float(__float2bfloat16(v.w));
            uint32_t off = (uint32_t)(row * PITCHB + c4 * 8);
            *(uint2*)(smem + SM_AH + off) = make_uint2(pkbf2(hx, hy), pkbf2(hz, hw));
            *(uint2*)(smem + SM_AL + off) =
                make_uint2(pkbf2(v.x - hx, v.y - hy), pkbf2(v.z - hz, v.w - hw));
        }
    }

    // PDL: wait for prep's Q stores to be visible, then pull B tiles.
    asm volatile("griddepcontrol.wait;" ::: "memory");

    const size_t Bbase = ((size_t)s * NN + (size_t)bj * TN) * DD;
    #pragma unroll
    for (int it = 0; it < 8; ++it) {
        int idx = it * 128 + tid;
        int row = idx >> 3, c = idx & 7;
        uint32_t so = (uint32_t)(row * PITCHB + c * 16);
        size_t go = (size_t)row * DD + c * 8;
        cpasync16(sb + SM_BH + so, g_Bh + Bbase + go);
        cpasync16(sb + SM_BL + so, g_Bl + Bbase + go);
    }
    asm volatile("cp.async.commit_group;" ::: "memory");
    asm volatile("cp.async.wait_group 0;" ::: "memory");
    __syncthreads();

    // ---- Per-lane ldmatrix base addresses ----
    const uint32_t a_lane = (uint32_t)((warp_m * 32 + (lid & 15)) * PITCHB +
                                       ((lid >> 4) * 8) * 2);
    const uint32_t b_lane = (uint32_t)((warp_n * 64 + ((lid >> 4) & 1) * 8 + (lid & 7)) * PITCHB +
                                       (((lid >> 3) & 1) * 8) * 2);

    float acc[2][8][4];
    #pragma unroll
    for (int mt = 0; mt < 2; ++mt)
        #pragma unroll
        for (int nt = 0; nt < 8; ++nt)
            #pragma unroll
            for (int r = 0; r < 4; ++r) acc[mt][nt][r] = 0.f;

    const uint32_t pAh = sb + SM_AH + a_lane, pAl = sb + SM_AL + a_lane;
    const uint32_t pBh = sb + SM_BH + b_lane, pBl = sb + SM_BL + b_lane;

    #pragma unroll
    for (int ks = 0; ks < 4; ++ks) {
        const uint32_t ko = (uint32_t)(ks * 32);
        uint32_t ah[2][4], al[2][4], bh[4][4], bl[4][4];
        #pragma unroll
        for (int mt = 0; mt < 2; ++mt)
            ldsm4(ah[mt], pAh + (uint32_t)(mt * 16 * PITCHB) + ko);
        #pragma unroll
        for (int nq = 0; nq < 4; ++nq)
            ldsm4(bh[nq], pBh + (uint32_t)(nq * 16 * PITCHB) + ko);
        #pragma unroll
        for (int mt = 0; mt < 2; ++mt)
            #pragma unroll
            for (int nq = 0; nq < 4; ++nq) {
                mma16816(acc[mt][2 * nq],     ah[mt], &bh[nq][0]);
                mma16816(acc[mt][2 * nq + 1], ah[mt], &bh[nq][2]);
            }
        #pragma unroll
        for (int mt = 0; mt < 2; ++mt)
            ldsm4(al[mt], pAl + (uint32_t)(mt * 16 * PITCHB) + ko);
        #pragma unroll
        for (int mt = 0; mt < 2; ++mt)
            #pragma unroll
            for (int nq = 0; nq < 4; ++nq) {
                mma16816(acc[mt][2 * nq],     al[mt], &bh[nq][0]);
                mma16816(acc[mt][2 * nq + 1], al[mt], &bh[nq][2]);
            }
        #pragma unroll
        for (int nq = 0; nq < 4; ++nq)
            ldsm4(bl[nq], pBl + (uint32_t)(nq * 16 * PITCHB) + ko);
        #pragma unroll
        for (int mt = 0; mt < 2; ++mt)
            #pragma unroll
            for (int nq = 0; nq < 4; ++nq) {
                mma16816(acc[mt][2 * nq],     ah[mt], &bl[nq][0]);
                mma16816(acc[mt][2 * nq + 1], ah[mt], &bl[nq][2]);
            }
    }

    // ---- Epilogue: direct register stores (streaming), both batch copies ----
    const float bv = *bias;
    const size_t BST = (size_t)SS * NN * NN;
    const size_t i_base = (size_t)bi * TM + warp_m * 32 + (lid >> 2);
    const size_t j_base = (size_t)bj * TN + warp_n * 64 + (lid & 3) * 2;

    #pragma unroll
    for (int mt = 0; mt < 2; ++mt) {
        #pragma unroll
        for (int nt = 0; nt < 8; ++nt) {
            float2 v0 = make_float2(acc[mt][nt][0] + bv, acc[mt][nt][1] + bv);
            float2 v1 = make_float2(acc[mt][nt][2] + bv, acc[mt][nt][3] + bv);
            float* d = out + ((size_t)s * NN + i_base + mt * 16) * NN + j_base + nt * 8;
            stcs2(d, v0);
            stcs2(d + 8 * NN, v1);
            stcs2(d + BST, v0);
            stcs2(d + BST + 8 * NN, v1);
        }
    }
}

// ---------------------------------------------------------------------------
// Launch: gemm uses programmatic stream serialization (PDL) to overlap
// its Q-independent prologue with prep's tail.
// ---------------------------------------------------------------------------
extern "C" void kernel_launch(void* const* d_in, const int* in_sizes, int n_in,
                              void* d_out, int out_size) {
    const float* x0   = (const float*)d_in[0];  // tensor0 (S,N,D)
    const float* x1   = (const float*)d_in[1];  // tensor1 (S,N,D)
    const float* W    = (const float*)d_in[2];  // kernel (D,D)
    const float* bias = (const float*)d_in[3];  // scalar
    float* out = (float*)d_out;                 // (2,S,N,N)

    cudaFuncSetAttribute(prep_mma, cudaFuncAttributeMaxDynamicSharedMemorySize, QSM_TOTAL);
    prep_mma<<<(SS * NN) / 128, 128, QSM_TOTAL>>>(x0, W);

    cudaFuncSetAttribute(gemm_mma, cudaFuncAttributeMaxDynamicSharedMemorySize, SM_TOTAL);
    cudaLaunchConfig_t cfg = {};
    cfg.gridDim = dim3(NN / TN, NN / TM, SS);
    cfg.blockDim = dim3(128, 1, 1);
    cfg.dynamicSmemBytes = SM_TOTAL;
    cfg.stream = 0;
    cudaLaunchAttribute attr[1];
    attr[0].id = cudaLaunchAttributeProgrammaticStreamSerialization;
    attr[0].val.programmaticStreamSerializationAllowed = 1;
    cfg.attrs = attr;
    cfg.numAttrs = 1;
    cudaLaunchKernelEx(&cfg, gemm_mma, x1, bias, out);
}